// round 12
// baseline (speedup 1.0000x reference)
#include <cuda_runtime.h>
#include <cuda_fp16.h>

// AreaSelfAttention fused kernel, round 12:
//   all GEMMs on tensor cores; 3 CTAs/SM (reg diet + y-on-Xh smem overlay).
// out = gamma * (Wv @ (Xw @ attn^T) + bv) + x

#define Cc   256
#define Hh   252
#define Ww   252
#define Aa   8
#define LDH  72     // row stride (halves) -> 144B rows, ldmatrix conflict-free

// smem byte offsets (total 56320 B -> 3 CTAs/SM possible)
#define OFF_QKH  0                              // qkh[64][LDH]h
#define OFF_ATH  (OFF_QKH + 64 * LDH * 2)       //  9216: ath[64][LDH]h
#define OFF_RED  (OFF_ATH + 64 * LDH * 2)       // 18432: red2[2][64] float2
#define OFF_XH   (OFF_RED + 1024)               // 19456: Xh[256][LDH]h (phase3 overlays y here)
#define SMEM_BYTES (OFF_XH + Cc * LDH * 2)      // 56320

// Fragment-packed fp16 weights (prep kernel fills once per launch).
// reg r of lane = A[mt*16 + gid + 8*(r&1)][ks*16 + 2*tg + 8*(r>>1)]
__device__ uint4 Wqk_pk4[4 * 16 * 32];     // [Wq;Wk] 64x256
__device__ uint4 Wv_pk4[16 * 16 * 32];     // Wv 256x256

__global__ void prep_pack(const float* __restrict__ Wq,
                          const float* __restrict__ Wk,
                          const float* __restrict__ Wv) {
    int u = blockIdx.x * 256 + threadIdx.x;      // grid 160 -> 40960 b32 outputs
    if (u < 8192) {
        int r = u & 3, lane = (u >> 2) & 31, ks = (u >> 7) & 15, mt = u >> 11;
        int gid = lane >> 2, tg = lane & 3;
        int row = mt * 16 + gid + 8 * (r & 1);
        int col = ks * 16 + 2 * tg + 8 * (r >> 1);
        const float* src = (row < 32) ? (Wq + row * Cc) : (Wk + (row - 32) * Cc);
        __half2 h = __floats2half2_rn(src[col], src[col + 1]);
        ((unsigned*)Wqk_pk4)[u] = *(unsigned*)&h;
    } else {
        int v = u - 8192;
        int r = v & 3, lane = (v >> 2) & 31, ks = (v >> 7) & 15, mt = v >> 11;
        int gid = lane >> 2, tg = lane & 3;
        int row = mt * 16 + gid + 8 * (r & 1);
        int col = ks * 16 + 2 * tg + 8 * (r >> 1);
        const float* src = Wv + (size_t)row * Cc;
        __half2 h = __floats2half2_rn(src[col], src[col + 1]);
        ((unsigned*)Wv_pk4)[v] = *(unsigned*)&h;
    }
}

static __device__ __forceinline__ void mma16816(float* d, const unsigned* a,
                                                unsigned b0, unsigned b1) {
    asm volatile(
        "mma.sync.aligned.m16n8k16.row.col.f32.f16.f16.f32 "
        "{%0,%1,%2,%3}, {%4,%5,%6,%7}, {%8,%9}, {%0,%1,%2,%3};"
        : "+f"(d[0]), "+f"(d[1]), "+f"(d[2]), "+f"(d[3])
        : "r"(a[0]), "r"(a[1]), "r"(a[2]), "r"(a[3]), "r"(b0), "r"(b1));
}
static __device__ __forceinline__ unsigned cvsm(const void* p) {
    return (unsigned)__cvta_generic_to_shared(p);
}
static __device__ __forceinline__ void ldsm_x4(unsigned* r, unsigned a) {
    asm volatile("ldmatrix.sync.aligned.m8n8.x4.shared.b16 {%0,%1,%2,%3}, [%4];"
                 : "=r"(r[0]), "=r"(r[1]), "=r"(r[2]), "=r"(r[3]) : "r"(a));
}
static __device__ __forceinline__ void ldsm_x4t(unsigned* r, unsigned a) {
    asm volatile("ldmatrix.sync.aligned.m8n8.x4.trans.shared.b16 {%0,%1,%2,%3}, [%4];"
                 : "=r"(r[0]), "=r"(r[1]), "=r"(r[2]), "=r"(r[3]) : "r"(a));
}

__global__ __launch_bounds__(256, 3)
void area_attn_kernel(const float* __restrict__ x,
                      const float* __restrict__ bq, const float* __restrict__ bk,
                      const float* __restrict__ bv,
                      const float* __restrict__ gamma,
                      float* __restrict__ out)
{
    extern __shared__ char smraw[];
    __half* qkh  = (__half*)(smraw + OFF_QKH); // [64][LDH] q rows 0..31, k rows 32..63
    __half* ath  = (__half*)(smraw + OFF_ATH); // [64][LDH] attn fp16
    float2* red2 = (float2*)(smraw + OFF_RED); // [2][64] (max, sum)
    __half* Xh   = (__half*)(smraw + OFF_XH);  // [256][LDH] window fp16
    __half* y    = Xh;                         // phase-3 output overlays Xh (safe: see split)

    const int t   = threadIdx.x;
    const int blk = blockIdx.x;
    const int bi  = blk >> 10;                 // 4096 = 4 * 32 * 32
    const int hi  = (blk >> 5) & 31;
    const int wi  = blk & 31;

    const float* xb = x + (size_t)bi * Cc * Hh * Ww;

    // ---------------- Phase 0: load x window -> Xh (fp16, zero-padded) -----
    #pragma unroll
    for (int it = 0; it < 16; ++it) {
        int idx4 = t + (it << 8);
        int c    = idx4 >> 4;
        int rem  = idx4 & 15;
        int iy   = rem >> 1;
        int ix4  = (rem & 1) << 2;
        int gy   = hi * Aa + iy;
        int gx   = wi * Aa + ix4;
        float4 v = make_float4(0.f, 0.f, 0.f, 0.f);
        if (gy < Hh && gx + 3 < Ww)
            v = *(const float4*)(xb + ((size_t)c * Hh + gy) * Ww + gx);
        __half2 h0 = __floats2half2_rn(v.x, v.y);
        __half2 h1 = __floats2half2_rn(v.z, v.w);
        uint2 pk;
        pk.x = *(unsigned*)&h0; pk.y = *(unsigned*)&h1;
        *(uint2*)(Xh + c * LDH + (rem << 2)) = pk;
    }
    __syncthreads();

    const int w    = t >> 5;
    const int lane = t & 31;
    const int gid  = lane >> 2;
    const int tg   = lane & 3;
    const int q4   = lane >> 3;
    const int row8 = lane & 7;
    const int l15  = lane & 15;
    const int lhi8 = (lane >> 4) << 3;     // 0 or 8

    // ---------------- Phase 1: qkh = fp16([Wq;Wk] @ Xw + bias) via MMA -----
    {
        const int mt1   = w & 3;
        const int nbase = (w >> 2) * 32;
        float d[4][4];
        #pragma unroll
        for (int nt = 0; nt < 4; ++nt)
            #pragma unroll
            for (int r = 0; r < 4; ++r) d[nt][r] = 0.f;

        uint4 av = Wqk_pk4[(mt1 * 16) * 32 + lane];
        #pragma unroll
        for (int ks = 0; ks < 16; ++ks) {
            uint4 nx;
            if (ks < 15) nx = Wqk_pk4[(mt1 * 16 + ks + 1) * 32 + lane];
            unsigned baddr = cvsm(Xh + (ks * 16 + l15) * LDH + nbase + lhi8);
            #pragma unroll
            for (int ntp = 0; ntp < 2; ++ntp) {
                unsigned bb[4];
                ldsm_x4t(bb, baddr + ntp * 32);
                mma16816(d[2 * ntp],     (const unsigned*)&av, bb[0], bb[1]);
                mma16816(d[2 * ntp + 1], (const unsigned*)&av, bb[2], bb[3]);
            }
            if (ks < 15) av = nx;
        }
        const int oc0 = mt1 * 16 + gid;
        const int oc1 = oc0 + 8;
        float bb0 = (mt1 < 2) ? bq[oc0] : bk[oc0 - 32];
        float bb1 = (mt1 < 2) ? bq[oc1] : bk[oc1 - 32];
        #pragma unroll
        for (int nt = 0; nt < 4; ++nt) {
            int pos = nbase + nt * 8 + 2 * tg;
            __half2 hA = __floats2half2_rn(d[nt][0] + bb0, d[nt][1] + bb0);
            __half2 hB = __floats2half2_rn(d[nt][2] + bb1, d[nt][3] + bb1);
            *(__half2*)(qkh + oc0 * LDH + pos) = hA;
            *(__half2*)(qkh + oc1 * LDH + pos) = hB;
        }
    }
    __syncthreads();

    // ---------------- Phase 2: logits via MMA + single-sync softmax --------
    {
        const int mt2   = w & 3;
        const int h2    = w >> 2;
        const int jbase = h2 * 32;
        float d[4][4];
        #pragma unroll
        for (int nt = 0; nt < 4; ++nt)
            #pragma unroll
            for (int r = 0; r < 4; ++r) d[nt][r] = 0.f;

        #pragma unroll
        for (int ks = 0; ks < 2; ++ks) {
            unsigned a[4];
            unsigned aaddr = cvsm(qkh + (ks * 16 + (q4 >> 1) * 8 + row8) * LDH
                                      + mt2 * 16 + (q4 & 1) * 8);
            ldsm_x4t(a, aaddr);
            unsigned baddr = cvsm(qkh + (32 + ks * 16 + l15) * LDH + jbase + lhi8);
            #pragma unroll
            for (int ntp = 0; ntp < 2; ++ntp) {
                unsigned bb[4];
                ldsm_x4t(bb, baddr + ntp * 32);
                mma16816(d[2 * ntp],     a, bb[0], bb[1]);
                mma16816(d[2 * ntp + 1], a, bb[2], bb[3]);
            }
        }

        const int iA = mt2 * 16 + gid;
        const int iB = iA + 8;
        float mA = d[0][0], mB = d[0][2];
        #pragma unroll
        for (int nt = 0; nt < 4; ++nt) {
            mA = fmaxf(mA, fmaxf(d[nt][0], d[nt][1]));
            mB = fmaxf(mB, fmaxf(d[nt][2], d[nt][3]));
        }
        mA = fmaxf(mA, __shfl_xor_sync(0xffffffffu, mA, 1));
        mA = fmaxf(mA, __shfl_xor_sync(0xffffffffu, mA, 2));
        mB = fmaxf(mB, __shfl_xor_sync(0xffffffffu, mB, 1));
        mB = fmaxf(mB, __shfl_xor_sync(0xffffffffu, mB, 2));
        float sA = 0.f, sB = 0.f;
        #pragma unroll
        for (int nt = 0; nt < 4; ++nt) {
            d[nt][0] = __expf(d[nt][0] - mA); sA += d[nt][0];
            d[nt][1] = __expf(d[nt][1] - mA); sA += d[nt][1];
            d[nt][2] = __expf(d[nt][2] - mB); sB += d[nt][2];
            d[nt][3] = __expf(d[nt][3] - mB); sB += d[nt][3];
        }
        sA += __shfl_xor_sync(0xffffffffu, sA, 1);
        sA += __shfl_xor_sync(0xffffffffu, sA, 2);
        sB += __shfl_xor_sync(0xffffffffu, sB, 1);
        sB += __shfl_xor_sync(0xffffffffu, sB, 2);
        if (tg == 0) {
            red2[h2 * 64 + iA] = make_float2(mA, sA);
            red2[h2 * 64 + iB] = make_float2(mB, sB);
        }
        __syncthreads();
        float2 c0A = red2[iA], c1A = red2[64 + iA];
        float2 c0B = red2[iB], c1B = red2[64 + iB];
        float gmA = fmaxf(c0A.x, c1A.x);
        float gmB = fmaxf(c0B.x, c1B.x);
        float totA = c0A.y * __expf(c0A.x - gmA) + c1A.y * __expf(c1A.x - gmA);
        float totB = c0B.y * __expf(c0B.x - gmB) + c1B.y * __expf(c1B.x - gmB);
        float facA = __expf(mA - gmA) / totA;
        float facB = __expf(mB - gmB) / totB;
        #pragma unroll
        for (int nt = 0; nt < 4; ++nt) {
            int j = jbase + nt * 8 + 2 * tg;
            *(__half2*)(ath + iA * LDH + j) =
                __floats2half2_rn(d[nt][0] * facA, d[nt][1] * facA);
            *(__half2*)(ath + iB * LDH + j) =
                __floats2half2_rn(d[nt][2] * facB, d[nt][3] * facB);
        }
    }
    __syncthreads();

    // ---------------- Phase 3: y = Xw @ attn^T via MMA; y overlays Xh ------
    // Split over mt halves: half h reads Xh rows [32w+16h, +16) then stores y
    // to exactly those rows (after all its reads). Other rows untouched.
    #pragma unroll
    for (int h = 0; h < 2; ++h) {
        float d[8][4];
        #pragma unroll
        for (int nt = 0; nt < 8; ++nt)
            #pragma unroll
            for (int r = 0; r < 4; ++r) d[nt][r] = 0.f;

        #pragma unroll
        for (int ks = 0; ks < 4; ++ks) {
            const int j0 = ks * 16;
            unsigned a[4];
            ldsm_x4(a, cvsm(Xh + (w * 32 + h * 16 + (q4 & 1) * 8 + row8) * LDH
                                + j0 + (q4 >> 1) * 8));
            #pragma unroll
            for (int ntp = 0; ntp < 4; ++ntp) {
                unsigned bb[4];
                ldsm_x4(bb, cvsm(ath + (ntp * 16 + lhi8 + row8) * LDH
                                     + j0 + (q4 & 1) * 8));
                mma16816(d[2 * ntp],     a, bb[0], bb[1]);
                mma16816(d[2 * ntp + 1], a, bb[2], bb[3]);
            }
        }
        const int e = w * 32 + h * 16 + gid;
        #pragma unroll
        for (int nt = 0; nt < 8; ++nt) {
            int i = nt * 8 + 2 * tg;
            *(__half2*)(y +  e      * LDH + i) = __floats2half2_rn(d[nt][0], d[nt][1]);
            *(__half2*)(y + (e + 8) * LDH + i) = __floats2half2_rn(d[nt][2], d[nt][3]);
        }
    }
    __syncthreads();

    // ---------------- Phase 4: out = Wv @ y via MMA + epilogue -------------
    // Split over nt halves (32 accums live); weights re-prefetched per half.
    {
        const float g = gamma[0];
        float* ob = out + (size_t)bi * Cc * Hh * Ww;
        #pragma unroll
        for (int h = 0; h < 2; ++h) {
            float d[2][4][4];
            #pragma unroll
            for (int mt = 0; mt < 2; ++mt)
                #pragma unroll
                for (int ntl = 0; ntl < 4; ++ntl)
                    #pragma unroll
                    for (int r = 0; r < 4; ++r) d[mt][ntl][r] = 0.f;

            uint4 av0 = Wv_pk4[((w * 2 + 0) * 16) * 32 + lane];
            uint4 av1 = Wv_pk4[((w * 2 + 1) * 16) * 32 + lane];
            #pragma unroll
            for (int ks = 0; ks < 16; ++ks) {
                uint4 nx0, nx1;
                if (ks < 15) {
                    nx0 = Wv_pk4[((w * 2 + 0) * 16 + ks + 1) * 32 + lane];
                    nx1 = Wv_pk4[((w * 2 + 1) * 16 + ks + 1) * 32 + lane];
                }
                unsigned baddr = cvsm(y + (ks * 16 + l15) * LDH + lhi8);
                #pragma unroll
                for (int ntp = 0; ntp < 2; ++ntp) {
                    unsigned bb[4];
                    ldsm_x4t(bb, baddr + (h * 2 + ntp) * 32);
                    mma16816(d[0][2 * ntp],     (const unsigned*)&av0, bb[0], bb[1]);
                    mma16816(d[0][2 * ntp + 1], (const unsigned*)&av0, bb[2], bb[3]);
                    mma16816(d[1][2 * ntp],     (const unsigned*)&av1, bb[0], bb[1]);
                    mma16816(d[1][2 * ntp + 1], (const unsigned*)&av1, bb[2], bb[3]);
                }
                if (ks < 15) { av0 = nx0; av1 = nx1; }
            }

            #pragma unroll
            for (int mt = 0; mt < 2; ++mt) {
                int cA = w * 32 + mt * 16 + gid;
                int cB = cA + 8;
                float bvA = bv[cA], bvB = bv[cB];
                #pragma unroll
                for (int ntl = 0; ntl < 4; ++ntl) {
                    int nt = h * 4 + ntl;
                    int gy = hi * Aa + nt;       // i = nt*8 + 2tg -> iy = nt
                    int gx = wi * Aa + 2 * tg;
                    if (gy < Hh && gx + 1 < Ww) {
                        size_t oA = ((size_t)cA * Hh + gy) * Ww + gx;
                        size_t oB = ((size_t)cB * Hh + gy) * Ww + gx;
                        float2 rA = *(const float2*)(xb + oA);
                        float2 rB = *(const float2*)(xb + oB);
                        float2 sA, sB;
                        sA.x = g * (d[mt][ntl][0] + bvA) + rA.x;
                        sA.y = g * (d[mt][ntl][1] + bvA) + rA.y;
                        sB.x = g * (d[mt][ntl][2] + bvB) + rB.x;
                        sB.y = g * (d[mt][ntl][3] + bvB) + rB.y;
                        *(float2*)(ob + oA) = sA;
                        *(float2*)(ob + oB) = sB;
                    }
                }
            }
        }
    }
}

extern "C" void kernel_launch(void* const* d_in, const int* in_sizes, int n_in,
                              void* d_out, int out_size) {
    (void)in_sizes; (void)n_in; (void)out_size;
    const float* x     = (const float*)d_in[0];
    const float* Wq    = (const float*)d_in[1];
    const float* bq    = (const float*)d_in[2];
    const float* Wk    = (const float*)d_in[3];
    const float* bk    = (const float*)d_in[4];
    const float* Wv    = (const float*)d_in[5];
    const float* bv    = (const float*)d_in[6];
    const float* gamma = (const float*)d_in[7];
    float* out = (float*)d_out;

    cudaFuncSetAttribute(area_attn_kernel,
                         cudaFuncAttributeMaxDynamicSharedMemorySize, SMEM_BYTES);

    prep_pack<<<160, 256>>>(Wq, Wk, Wv);
    area_attn_kernel<<<4096, 256, SMEM_BYTES>>>(x, bq, bk, bv, gamma, out);
}

// round 13
// speedup vs baseline: 1.0808x; 1.0808x over previous
#include <cuda_runtime.h>
#include <cuda_fp16.h>

// AreaSelfAttention fused kernel, round 13:
//   all GEMMs on tensor cores; 2 CTAs/SM; explicit B-fragment double-buffering
//   (ldsm for ks+1 issued before MMAs of ks) to overlap L1 and tensor pipes.
// out = gamma * (Wv @ (Xw @ attn^T) + bv) + x

#define Cc   256
#define Hh   252
#define Ww   252
#define Aa   8
#define LDH  72     // row stride (halves) -> 144B rows, ldmatrix conflict-free

// smem byte offsets (total 56320 B)
#define OFF_QKH  0                              // qkh[64][LDH]h
#define OFF_ATH  (OFF_QKH + 64 * LDH * 2)       //  9216: ath[64][LDH]h
#define OFF_RED  (OFF_ATH + 64 * LDH * 2)       // 18432: red2[2][64] float2
#define OFF_XH   (OFF_RED + 1024)               // 19456: Xh[256][LDH]h (phase3 overlays y here)
#define SMEM_BYTES (OFF_XH + Cc * LDH * 2)      // 56320

// Fragment-packed fp16 weights (prep kernel fills once per launch).
// reg r of lane = A[mt*16 + gid + 8*(r&1)][ks*16 + 2*tg + 8*(r>>1)]
__device__ uint4 Wqk_pk4[4 * 16 * 32];     // [Wq;Wk] 64x256
__device__ uint4 Wv_pk4[16 * 16 * 32];     // Wv 256x256

__global__ void prep_pack(const float* __restrict__ Wq,
                          const float* __restrict__ Wk,
                          const float* __restrict__ Wv) {
    int u = blockIdx.x * 256 + threadIdx.x;      // grid 160 -> 40960 b32 outputs
    if (u < 8192) {
        int r = u & 3, lane = (u >> 2) & 31, ks = (u >> 7) & 15, mt = u >> 11;
        int gid = lane >> 2, tg = lane & 3;
        int row = mt * 16 + gid + 8 * (r & 1);
        int col = ks * 16 + 2 * tg + 8 * (r >> 1);
        const float* src = (row < 32) ? (Wq + row * Cc) : (Wk + (row - 32) * Cc);
        __half2 h = __floats2half2_rn(src[col], src[col + 1]);
        ((unsigned*)Wqk_pk4)[u] = *(unsigned*)&h;
    } else {
        int v = u - 8192;
        int r = v & 3, lane = (v >> 2) & 31, ks = (v >> 7) & 15, mt = v >> 11;
        int gid = lane >> 2, tg = lane & 3;
        int row = mt * 16 + gid + 8 * (r & 1);
        int col = ks * 16 + 2 * tg + 8 * (r >> 1);
        const float* src = Wv + (size_t)row * Cc;
        __half2 h = __floats2half2_rn(src[col], src[col + 1]);
        ((unsigned*)Wv_pk4)[v] = *(unsigned*)&h;
    }
}

static __device__ __forceinline__ void mma16816(float* d, const unsigned* a,
                                                unsigned b0, unsigned b1) {
    asm volatile(
        "mma.sync.aligned.m16n8k16.row.col.f32.f16.f16.f32 "
        "{%0,%1,%2,%3}, {%4,%5,%6,%7}, {%8,%9}, {%0,%1,%2,%3};"
        : "+f"(d[0]), "+f"(d[1]), "+f"(d[2]), "+f"(d[3])
        : "r"(a[0]), "r"(a[1]), "r"(a[2]), "r"(a[3]), "r"(b0), "r"(b1));
}
static __device__ __forceinline__ unsigned cvsm(const void* p) {
    return (unsigned)__cvta_generic_to_shared(p);
}
static __device__ __forceinline__ void ldsm_x4(unsigned* r, unsigned a) {
    asm volatile("ldmatrix.sync.aligned.m8n8.x4.shared.b16 {%0,%1,%2,%3}, [%4];"
                 : "=r"(r[0]), "=r"(r[1]), "=r"(r[2]), "=r"(r[3]) : "r"(a));
}
static __device__ __forceinline__ void ldsm_x4t(unsigned* r, unsigned a) {
    asm volatile("ldmatrix.sync.aligned.m8n8.x4.trans.shared.b16 {%0,%1,%2,%3}, [%4];"
                 : "=r"(r[0]), "=r"(r[1]), "=r"(r[2]), "=r"(r[3]) : "r"(a));
}

__global__ __launch_bounds__(256, 2)
void area_attn_kernel(const float* __restrict__ x,
                      const float* __restrict__ bq, const float* __restrict__ bk,
                      const float* __restrict__ bv,
                      const float* __restrict__ gamma,
                      float* __restrict__ out)
{
    extern __shared__ char smraw[];
    __half* qkh  = (__half*)(smraw + OFF_QKH); // [64][LDH] q rows 0..31, k rows 32..63
    __half* ath  = (__half*)(smraw + OFF_ATH); // [64][LDH] attn fp16
    float2* red2 = (float2*)(smraw + OFF_RED); // [2][64] (max, sum)
    __half* Xh   = (__half*)(smraw + OFF_XH);  // [256][LDH] window fp16
    __half* y    = Xh;                         // phase-3 output overlays Xh (safe split)

    const int t   = threadIdx.x;
    const int blk = blockIdx.x;
    const int bi  = blk >> 10;                 // 4096 = 4 * 32 * 32
    const int hi  = (blk >> 5) & 31;
    const int wi  = blk & 31;

    const float* xb = x + (size_t)bi * Cc * Hh * Ww;

    // ---------------- Phase 0: load x window -> Xh (fp16, zero-padded) -----
    #pragma unroll
    for (int it = 0; it < 16; ++it) {
        int idx4 = t + (it << 8);
        int c    = idx4 >> 4;
        int rem  = idx4 & 15;
        int iy   = rem >> 1;
        int ix4  = (rem & 1) << 2;
        int gy   = hi * Aa + iy;
        int gx   = wi * Aa + ix4;
        float4 v = make_float4(0.f, 0.f, 0.f, 0.f);
        if (gy < Hh && gx + 3 < Ww)
            v = *(const float4*)(xb + ((size_t)c * Hh + gy) * Ww + gx);
        __half2 h0 = __floats2half2_rn(v.x, v.y);
        __half2 h1 = __floats2half2_rn(v.z, v.w);
        uint2 pk;
        pk.x = *(unsigned*)&h0; pk.y = *(unsigned*)&h1;
        *(uint2*)(Xh + c * LDH + (rem << 2)) = pk;
    }
    __syncthreads();

    const int w    = t >> 5;
    const int lane = t & 31;
    const int gid  = lane >> 2;
    const int tg   = lane & 3;
    const int q4   = lane >> 3;
    const int row8 = lane & 7;
    const int l15  = lane & 15;
    const int lhi8 = (lane >> 4) << 3;     // 0 or 8

    // ---------------- Phase 1: qkh = fp16([Wq;Wk] @ Xw + bias) via MMA -----
    // Double-buffered B; prefetched A (weights).
    {
        const int mt1   = w & 3;
        const int nbase = (w >> 2) * 32;
        float d[4][4];
        #pragma unroll
        for (int nt = 0; nt < 4; ++nt)
            #pragma unroll
            for (int r = 0; r < 4; ++r) d[nt][r] = 0.f;

        uint4 av = Wqk_pk4[(mt1 * 16) * 32 + lane];
        unsigned bb[2][2][4];
        {
            unsigned b0 = cvsm(Xh + l15 * LDH + nbase + lhi8);
            ldsm_x4t(bb[0][0], b0);
            ldsm_x4t(bb[0][1], b0 + 32);
        }
        #pragma unroll
        for (int ks = 0; ks < 16; ++ks) {
            const int cur = ks & 1, nxt = cur ^ 1;
            uint4 nx;
            if (ks < 15) {
                unsigned bn = cvsm(Xh + ((ks + 1) * 16 + l15) * LDH + nbase + lhi8);
                ldsm_x4t(bb[nxt][0], bn);
                ldsm_x4t(bb[nxt][1], bn + 32);
                nx = Wqk_pk4[(mt1 * 16 + ks + 1) * 32 + lane];
            }
            mma16816(d[0], (const unsigned*)&av, bb[cur][0][0], bb[cur][0][1]);
            mma16816(d[1], (const unsigned*)&av, bb[cur][0][2], bb[cur][0][3]);
            mma16816(d[2], (const unsigned*)&av, bb[cur][1][0], bb[cur][1][1]);
            mma16816(d[3], (const unsigned*)&av, bb[cur][1][2], bb[cur][1][3]);
            if (ks < 15) av = nx;
        }
        const int oc0 = mt1 * 16 + gid;
        const int oc1 = oc0 + 8;
        float bb0 = (mt1 < 2) ? bq[oc0] : bk[oc0 - 32];
        float bb1 = (mt1 < 2) ? bq[oc1] : bk[oc1 - 32];
        #pragma unroll
        for (int nt = 0; nt < 4; ++nt) {
            int pos = nbase + nt * 8 + 2 * tg;
            __half2 hA = __floats2half2_rn(d[nt][0] + bb0, d[nt][1] + bb0);
            __half2 hB = __floats2half2_rn(d[nt][2] + bb1, d[nt][3] + bb1);
            *(__half2*)(qkh + oc0 * LDH + pos) = hA;
            *(__half2*)(qkh + oc1 * LDH + pos) = hB;
        }
    }
    __syncthreads();

    // ---------------- Phase 2: logits via MMA + single-sync softmax --------
    {
        const int mt2   = w & 3;
        const int h2    = w >> 2;
        const int jbase = h2 * 32;
        float d[4][4];
        #pragma unroll
        for (int nt = 0; nt < 4; ++nt)
            #pragma unroll
            for (int r = 0; r < 4; ++r) d[nt][r] = 0.f;

        #pragma unroll
        for (int ks = 0; ks < 2; ++ks) {
            unsigned a[4];
            unsigned aaddr = cvsm(qkh + (ks * 16 + (q4 >> 1) * 8 + row8) * LDH
                                      + mt2 * 16 + (q4 & 1) * 8);
            ldsm_x4t(a, aaddr);
            unsigned baddr = cvsm(qkh + (32 + ks * 16 + l15) * LDH + jbase + lhi8);
            #pragma unroll
            for (int ntp = 0; ntp < 2; ++ntp) {
                unsigned bbq[4];
                ldsm_x4t(bbq, baddr + ntp * 32);
                mma16816(d[2 * ntp],     a, bbq[0], bbq[1]);
                mma16816(d[2 * ntp + 1], a, bbq[2], bbq[3]);
            }
        }

        const int iA = mt2 * 16 + gid;
        const int iB = iA + 8;
        float mA = d[0][0], mB = d[0][2];
        #pragma unroll
        for (int nt = 0; nt < 4; ++nt) {
            mA = fmaxf(mA, fmaxf(d[nt][0], d[nt][1]));
            mB = fmaxf(mB, fmaxf(d[nt][2], d[nt][3]));
        }
        mA = fmaxf(mA, __shfl_xor_sync(0xffffffffu, mA, 1));
        mA = fmaxf(mA, __shfl_xor_sync(0xffffffffu, mA, 2));
        mB = fmaxf(mB, __shfl_xor_sync(0xffffffffu, mB, 1));
        mB = fmaxf(mB, __shfl_xor_sync(0xffffffffu, mB, 2));
        float sA = 0.f, sB = 0.f;
        #pragma unroll
        for (int nt = 0; nt < 4; ++nt) {
            d[nt][0] = __expf(d[nt][0] - mA); sA += d[nt][0];
            d[nt][1] = __expf(d[nt][1] - mA); sA += d[nt][1];
            d[nt][2] = __expf(d[nt][2] - mB); sB += d[nt][2];
            d[nt][3] = __expf(d[nt][3] - mB); sB += d[nt][3];
        }
        sA += __shfl_xor_sync(0xffffffffu, sA, 1);
        sA += __shfl_xor_sync(0xffffffffu, sA, 2);
        sB += __shfl_xor_sync(0xffffffffu, sB, 1);
        sB += __shfl_xor_sync(0xffffffffu, sB, 2);
        if (tg == 0) {
            red2[h2 * 64 + iA] = make_float2(mA, sA);
            red2[h2 * 64 + iB] = make_float2(mB, sB);
        }
        __syncthreads();
        float2 c0A = red2[iA], c1A = red2[64 + iA];
        float2 c0B = red2[iB], c1B = red2[64 + iB];
        float gmA = fmaxf(c0A.x, c1A.x);
        float gmB = fmaxf(c0B.x, c1B.x);
        float totA = c0A.y * __expf(c0A.x - gmA) + c1A.y * __expf(c1A.x - gmA);
        float totB = c0B.y * __expf(c0B.x - gmB) + c1B.y * __expf(c1B.x - gmB);
        float facA = __expf(mA - gmA) / totA;
        float facB = __expf(mB - gmB) / totB;
        #pragma unroll
        for (int nt = 0; nt < 4; ++nt) {
            int j = jbase + nt * 8 + 2 * tg;
            *(__half2*)(ath + iA * LDH + j) =
                __floats2half2_rn(d[nt][0] * facA, d[nt][1] * facA);
            *(__half2*)(ath + iB * LDH + j) =
                __floats2half2_rn(d[nt][2] * facB, d[nt][3] * facB);
        }
    }
    __syncthreads();

    // ---------------- Phase 3: y = Xw @ attn^T via MMA; y overlays Xh ------
    // Split over mt halves; A and B double-buffered across ks.
    #pragma unroll
    for (int h = 0; h < 2; ++h) {
        float d[8][4];
        #pragma unroll
        for (int nt = 0; nt < 8; ++nt)
            #pragma unroll
            for (int r = 0; r < 4; ++r) d[nt][r] = 0.f;

        unsigned a[2][4], bb[2][4][4];
        ldsm_x4(a[0], cvsm(Xh + (w * 32 + h * 16 + (q4 & 1) * 8 + row8) * LDH
                               + (q4 >> 1) * 8));
        #pragma unroll
        for (int ntp = 0; ntp < 4; ++ntp)
            ldsm_x4(bb[0][ntp], cvsm(ath + (ntp * 16 + lhi8 + row8) * LDH
                                         + (q4 & 1) * 8));
        #pragma unroll
        for (int ks = 0; ks < 4; ++ks) {
            const int cur = ks & 1, nxt = cur ^ 1;
            if (ks < 3) {
                const int j1 = (ks + 1) * 16;
                ldsm_x4(a[nxt], cvsm(Xh + (w * 32 + h * 16 + (q4 & 1) * 8 + row8) * LDH
                                         + j1 + (q4 >> 1) * 8));
                #pragma unroll
                for (int ntp = 0; ntp < 4; ++ntp)
                    ldsm_x4(bb[nxt][ntp], cvsm(ath + (ntp * 16 + lhi8 + row8) * LDH
                                                   + j1 + (q4 & 1) * 8));
            }
            #pragma unroll
            for (int ntp = 0; ntp < 4; ++ntp) {
                mma16816(d[2 * ntp],     a[cur], bb[cur][ntp][0], bb[cur][ntp][1]);
                mma16816(d[2 * ntp + 1], a[cur], bb[cur][ntp][2], bb[cur][ntp][3]);
            }
        }
        const int e = w * 32 + h * 16 + gid;
        #pragma unroll
        for (int nt = 0; nt < 8; ++nt) {
            int i = nt * 8 + 2 * tg;
            *(__half2*)(y +  e      * LDH + i) = __floats2half2_rn(d[nt][0], d[nt][1]);
            *(__half2*)(y + (e + 8) * LDH + i) = __floats2half2_rn(d[nt][2], d[nt][3]);
        }
    }
    __syncthreads();

    // ---------------- Phase 4: out = Wv @ y via MMA + epilogue -------------
    // Split over nt halves; B double-buffered; weights prefetched.
    {
        const float g = gamma[0];
        float* ob = out + (size_t)bi * Cc * Hh * Ww;
        #pragma unroll
        for (int h = 0; h < 2; ++h) {
            float d[2][4][4];
            #pragma unroll
            for (int mt = 0; mt < 2; ++mt)
                #pragma unroll
                for (int ntl = 0; ntl < 4; ++ntl)
                    #pragma unroll
                    for (int r = 0; r < 4; ++r) d[mt][ntl][r] = 0.f;

            uint4 av0 = Wv_pk4[((w * 2 + 0) * 16) * 32 + lane];
            uint4 av1 = Wv_pk4[((w * 2 + 1) * 16) * 32 + lane];
            unsigned bb[2][2][4];
            {
                unsigned b0 = cvsm(y + l15 * LDH + lhi8);
                ldsm_x4t(bb[0][0], b0 + (h * 2 + 0) * 32);
                ldsm_x4t(bb[0][1], b0 + (h * 2 + 1) * 32);
            }
            #pragma unroll
            for (int ks = 0; ks < 16; ++ks) {
                const int cur = ks & 1, nxt = cur ^ 1;
                uint4 nx0, nx1;
                if (ks < 15) {
                    unsigned bn = cvsm(y + ((ks + 1) * 16 + l15) * LDH + lhi8);
                    ldsm_x4t(bb[nxt][0], bn + (h * 2 + 0) * 32);
                    ldsm_x4t(bb[nxt][1], bn + (h * 2 + 1) * 32);
                    nx0 = Wv_pk4[((w * 2 + 0) * 16 + ks + 1) * 32 + lane];
                    nx1 = Wv_pk4[((w * 2 + 1) * 16 + ks + 1) * 32 + lane];
                }
                #pragma unroll
                for (int ntp = 0; ntp < 2; ++ntp) {
                    mma16816(d[0][2 * ntp],     (const unsigned*)&av0, bb[cur][ntp][0], bb[cur][ntp][1]);
                    mma16816(d[0][2 * ntp + 1], (const unsigned*)&av0, bb[cur][ntp][2], bb[cur][ntp][3]);
                    mma16816(d[1][2 * ntp],     (const unsigned*)&av1, bb[cur][ntp][0], bb[cur][ntp][1]);
                    mma16816(d[1][2 * ntp + 1], (const unsigned*)&av1, bb[cur][ntp][2], bb[cur][ntp][3]);
                }
                if (ks < 15) { av0 = nx0; av1 = nx1; }
            }

            #pragma unroll
            for (int mt = 0; mt < 2; ++mt) {
                int cA = w * 32 + mt * 16 + gid;
                int cB = cA + 8;
                float bvA = bv[cA], bvB = bv[cB];
                #pragma unroll
                for (int ntl = 0; ntl < 4; ++ntl) {
                    int nt = h * 4 + ntl;
                    int gy = hi * Aa + nt;       // i = nt*8 + 2tg -> iy = nt
                    int gx = wi * Aa + 2 * tg;
                    if (gy < Hh && gx + 1 < Ww) {
                        size_t oA = ((size_t)cA * Hh + gy) * Ww + gx;
                        size_t oB = ((size_t)cB * Hh + gy) * Ww + gx;
                        float2 rA = *(const float2*)(xb + oA);
                        float2 rB = *(const float2*)(xb + oB);
                        float2 sA, sB;
                        sA.x = g * (d[mt][ntl][0] + bvA) + rA.x;
                        sA.y = g * (d[mt][ntl][1] + bvA) + rA.y;
                        sB.x = g * (d[mt][ntl][2] + bvB) + rB.x;
                        sB.y = g * (d[mt][ntl][3] + bvB) + rB.y;
                        *(float2*)(ob + oA) = sA;
                        *(float2*)(ob + oB) = sB;
                    }
                }
            }
        }
    }
}

extern "C" void kernel_launch(void* const* d_in, const int* in_sizes, int n_in,
                              void* d_out, int out_size) {
    (void)in_sizes; (void)n_in; (void)out_size;
    const float* x     = (const float*)d_in[0];
    const float* Wq    = (const float*)d_in[1];
    const float* bq    = (const float*)d_in[2];
    const float* Wk    = (const float*)d_in[3];
    const float* bk    = (const float*)d_in[4];
    const float* Wv    = (const float*)d_in[5];
    const float* bv    = (const float*)d_in[6];
    const float* gamma = (const float*)d_in[7];
    float* out = (float*)d_out;

    cudaFuncSetAttribute(area_attn_kernel,
                         cudaFuncAttributeMaxDynamicSharedMemorySize, SMEM_BYTES);

    prep_pack<<<160, 256>>>(Wq, Wk, Wv);
    area_attn_kernel<<<4096, 256, SMEM_BYTES>>>(x, bq, bk, bv, gamma, out);
}